// round 2
// baseline (speedup 1.0000x reference)
#include <cuda_runtime.h>
#include <math.h>

// Problem shape (fixed by the dataset)
#define BB 8
#define SS 2048
#define DD 1024

// Scratch for proj = X @ W^T + b   (64 MB, allocation-guard-safe)
__device__ float g_proj[(size_t)BB * SS * DD];

// ---------------- Tiled fp32 GEMM parameters ----------------
#define BM 128
#define BN 128
#define BKT 16
#define TM 8
#define TN 8
#define PAD 4   // smem row padding (keeps 16B alignment, cuts store conflicts)

// ============================================================
// NT GEMM: C[M,N] = A[M,K] * B[N,K]^T (+bias[n])
// Both A and B are K-contiguous (row-major with K innermost).
// Batched via blockIdx.z with explicit strides.
// ============================================================
__global__ __launch_bounds__(256, 2) void gemm_nt(
    const float* __restrict__ A, const float* __restrict__ B,
    float* __restrict__ C, const float* __restrict__ bias,
    int M, int N, int K,
    long long strideA, long long strideB, long long strideC)
{
    __shared__ float As[BKT][BM + PAD];
    __shared__ float Bs[BKT][BN + PAD];

    const float* Ab = A + (long long)blockIdx.z * strideA;
    const float* Bb = B + (long long)blockIdx.z * strideB;
    float*       Cb = C + (long long)blockIdx.z * strideC;

    const int tid  = threadIdx.x;
    const int row0 = blockIdx.y * BM;
    const int col0 = blockIdx.x * BN;

    const int tx = tid % (BN / TN);  // 0..15
    const int ty = tid / (BN / TN);  // 0..15

    // Load indexing: each thread loads 2 float4 from A and 2 from B per K-tile
    const int lrow  = tid / 4;        // 0..63
    const int lcol4 = (tid % 4) * 4;  // 0,4,8,12

    float acc[TM][TN];
#pragma unroll
    for (int i = 0; i < TM; i++)
#pragma unroll
        for (int j = 0; j < TN; j++) acc[i][j] = 0.f;

    for (int k0 = 0; k0 < K; k0 += BKT) {
#pragma unroll
        for (int r = 0; r < 2; r++) {
            int m = lrow + r * 64;
            float4 v = *reinterpret_cast<const float4*>(
                &Ab[(long long)(row0 + m) * K + k0 + lcol4]);
            As[lcol4 + 0][m] = v.x;
            As[lcol4 + 1][m] = v.y;
            As[lcol4 + 2][m] = v.z;
            As[lcol4 + 3][m] = v.w;
        }
#pragma unroll
        for (int r = 0; r < 2; r++) {
            int n = lrow + r * 64;
            float4 v = *reinterpret_cast<const float4*>(
                &Bb[(long long)(col0 + n) * K + k0 + lcol4]);
            Bs[lcol4 + 0][n] = v.x;
            Bs[lcol4 + 1][n] = v.y;
            Bs[lcol4 + 2][n] = v.z;
            Bs[lcol4 + 3][n] = v.w;
        }
        __syncthreads();

#pragma unroll
        for (int k = 0; k < BKT; k++) {
            float4 a0 = *reinterpret_cast<const float4*>(&As[k][ty * TM]);
            float4 a1 = *reinterpret_cast<const float4*>(&As[k][ty * TM + 4]);
            float4 b0 = *reinterpret_cast<const float4*>(&Bs[k][tx * TN]);
            float4 b1 = *reinterpret_cast<const float4*>(&Bs[k][tx * TN + 4]);
            float ar[TM] = {a0.x, a0.y, a0.z, a0.w, a1.x, a1.y, a1.z, a1.w};
            float br[TN] = {b0.x, b0.y, b0.z, b0.w, b1.x, b1.y, b1.z, b1.w};
#pragma unroll
            for (int i = 0; i < TM; i++)
#pragma unroll
                for (int j = 0; j < TN; j++) acc[i][j] += ar[i] * br[j];
        }
        __syncthreads();
    }

#pragma unroll
    for (int i = 0; i < TM; i++) {
        long long m = row0 + ty * TM + i;
#pragma unroll
        for (int j = 0; j < TN; j += 4) {
            int n = col0 + tx * TN + j;
            float4 v;
            v.x = acc[i][j + 0];
            v.y = acc[i][j + 1];
            v.z = acc[i][j + 2];
            v.w = acc[i][j + 3];
            if (bias) {
                v.x += bias[n + 0];
                v.y += bias[n + 1];
                v.z += bias[n + 2];
                v.w += bias[n + 3];
            }
            *reinterpret_cast<float4*>(&Cb[m * N + n]) = v;
        }
    }
}

// ============================================================
// NN GEMM: C[M,N] = A[M,K] * B[K,N]
// A is K-contiguous, B is N-contiguous. Batched via blockIdx.z.
// ============================================================
__global__ __launch_bounds__(256, 2) void gemm_nn(
    const float* __restrict__ A, const float* __restrict__ B,
    float* __restrict__ C,
    int M, int N, int K,
    long long strideA, long long strideB, long long strideC)
{
    __shared__ float As[BKT][BM + PAD];
    __shared__ float Bs[BKT][BN + PAD];

    const float* Ab = A + (long long)blockIdx.z * strideA;
    const float* Bb = B + (long long)blockIdx.z * strideB;
    float*       Cb = C + (long long)blockIdx.z * strideC;

    const int tid  = threadIdx.x;
    const int row0 = blockIdx.y * BM;
    const int col0 = blockIdx.x * BN;

    const int tx = tid % (BN / TN);
    const int ty = tid / (BN / TN);

    const int lrow  = tid / 4;        // A load: 0..63
    const int lcol4 = (tid % 4) * 4;

    const int bkr  = tid / 32;        // B load: k-row 0..7
    const int bc4  = (tid % 32) * 4;  // col within tile

    float acc[TM][TN];
#pragma unroll
    for (int i = 0; i < TM; i++)
#pragma unroll
        for (int j = 0; j < TN; j++) acc[i][j] = 0.f;

    for (int k0 = 0; k0 < K; k0 += BKT) {
#pragma unroll
        for (int r = 0; r < 2; r++) {
            int m = lrow + r * 64;
            float4 v = *reinterpret_cast<const float4*>(
                &Ab[(long long)(row0 + m) * K + k0 + lcol4]);
            As[lcol4 + 0][m] = v.x;
            As[lcol4 + 1][m] = v.y;
            As[lcol4 + 2][m] = v.z;
            As[lcol4 + 3][m] = v.w;
        }
#pragma unroll
        for (int r = 0; r < 2; r++) {
            int k = bkr + r * 8;
            float4 v = *reinterpret_cast<const float4*>(
                &Bb[(long long)(k0 + k) * N + col0 + bc4]);
            *reinterpret_cast<float4*>(&Bs[k][bc4]) = v;
        }
        __syncthreads();

#pragma unroll
        for (int k = 0; k < BKT; k++) {
            float4 a0 = *reinterpret_cast<const float4*>(&As[k][ty * TM]);
            float4 a1 = *reinterpret_cast<const float4*>(&As[k][ty * TM + 4]);
            float4 b0 = *reinterpret_cast<const float4*>(&Bs[k][tx * TN]);
            float4 b1 = *reinterpret_cast<const float4*>(&Bs[k][tx * TN + 4]);
            float ar[TM] = {a0.x, a0.y, a0.z, a0.w, a1.x, a1.y, a1.z, a1.w};
            float br[TN] = {b0.x, b0.y, b0.z, b0.w, b1.x, b1.y, b1.z, b1.w};
#pragma unroll
            for (int i = 0; i < TM; i++)
#pragma unroll
                for (int j = 0; j < TN; j++) acc[i][j] += ar[i] * br[j];
        }
        __syncthreads();
    }

#pragma unroll
    for (int i = 0; i < TM; i++) {
        long long m = row0 + ty * TM + i;
#pragma unroll
        for (int j = 0; j < TN; j += 4) {
            int n = col0 + tx * TN + j;
            float4 v;
            v.x = acc[i][j + 0];
            v.y = acc[i][j + 1];
            v.z = acc[i][j + 2];
            v.w = acc[i][j + 3];
            *reinterpret_cast<float4*>(&Cb[m * N + n]) = v;
        }
    }
}

// ============================================================
// In-place row softmax over rows of length SS (2048).
// One block (256 threads) per row; row fits in 8 regs/thread.
// ============================================================
__device__ __forceinline__ float warp_max(float v) {
#pragma unroll
    for (int o = 16; o > 0; o >>= 1) v = fmaxf(v, __shfl_xor_sync(0xFFFFFFFFu, v, o));
    return v;
}
__device__ __forceinline__ float warp_sum(float v) {
#pragma unroll
    for (int o = 16; o > 0; o >>= 1) v += __shfl_xor_sync(0xFFFFFFFFu, v, o);
    return v;
}

__global__ __launch_bounds__(256) void softmax_rows(float* __restrict__ attn)
{
    __shared__ float red[8];
    float* row = attn + (long long)blockIdx.x * SS;
    const int tid  = threadIdx.x;
    const int lane = tid & 31;
    const int wid  = tid >> 5;

    float4 v[2];
    v[0] = *reinterpret_cast<const float4*>(&row[(tid) * 4]);
    v[1] = *reinterpret_cast<const float4*>(&row[(tid + 256) * 4]);

    float mx = -INFINITY;
#pragma unroll
    for (int i = 0; i < 2; i++) {
        mx = fmaxf(mx, fmaxf(fmaxf(v[i].x, v[i].y), fmaxf(v[i].z, v[i].w)));
    }
    mx = warp_max(mx);
    if (lane == 0) red[wid] = mx;
    __syncthreads();
    if (wid == 0) {
        // FIX (R1 bug): only lanes 0..7 carry a valid partial; lanes 8..31
        // must contribute the identity element, otherwise each partial is
        // counted 4x (this made every softmax row sum to 0.25 -> rel_err 0.75).
        float t = (lane < 8) ? red[lane] : -INFINITY;
        t = warp_max(t);
        if (lane == 0) red[0] = t;
    }
    __syncthreads();
    mx = red[0];
    __syncthreads();

    float s = 0.f;
#pragma unroll
    for (int i = 0; i < 2; i++) {
        v[i].x = expf(v[i].x - mx); s += v[i].x;
        v[i].y = expf(v[i].y - mx); s += v[i].y;
        v[i].z = expf(v[i].z - mx); s += v[i].z;
        v[i].w = expf(v[i].w - mx); s += v[i].w;
    }
    s = warp_sum(s);
    if (lane == 0) red[wid] = s;
    __syncthreads();
    if (wid == 0) {
        float t = (lane < 8) ? red[lane] : 0.0f;   // FIX: identity for extra lanes
        t = warp_sum(t);
        if (lane == 0) red[0] = t;
    }
    __syncthreads();
    float inv = 1.0f / red[0];

#pragma unroll
    for (int i = 0; i < 2; i++) {
        v[i].x *= inv; v[i].y *= inv; v[i].z *= inv; v[i].w *= inv;
    }
    *reinterpret_cast<float4*>(&row[(tid) * 4])       = v[0];
    *reinterpret_cast<float4*>(&row[(tid + 256) * 4]) = v[1];
}

// ============================================================
// kernel_launch
// Inputs (metadata order): lstm_output [8,2048,1024] f32, W [1024,1024] f32, b [1024] f32
// Output: context [8,2048,1024] f32  ||  attn_weights [8,2048,2048] f32 (concatenated)
// ============================================================
extern "C" void kernel_launch(void* const* d_in, const int* in_sizes, int n_in,
                              void* d_out, int out_size)
{
    const float* X    = (const float*)d_in[0];
    const float* W    = (const float*)d_in[1];
    const float* bias = (const float*)d_in[2];

    float* ctx  = (float*)d_out;                                  // [8,2048,1024]
    float* attn = (float*)d_out + (size_t)BB * SS * DD;           // [8,2048,2048]

    float* proj = nullptr;
    cudaGetSymbolAddress((void**)&proj, g_proj);

    const long long sXD = (long long)SS * DD;   // per-batch X / proj / ctx stride
    const long long sA  = (long long)SS * SS;   // per-batch attn stride

    // GEMM1: proj[M=16384, N=1024] = X[16384,1024] * W[1024,1024]^T + b
    {
        dim3 grid(DD / BN, (BB * SS) / BM, 1);
        gemm_nt<<<grid, 256>>>(X, W, proj, bias,
                               BB * SS, DD, DD, 0, 0, 0);
    }

    // GEMM2 (batched): attn[b] = X[b] (2048x1024) * proj[b]^T (1024x2048)
    {
        dim3 grid(SS / BN, SS / BM, BB);
        gemm_nt<<<grid, 256>>>(X, proj, attn, nullptr,
                               SS, SS, DD, sXD, sXD, sA);
    }

    // Softmax over last dim, in place in d_out
    softmax_rows<<<BB * SS, 256>>>(attn);

    // GEMM3 (batched): ctx[b] = attn[b] (2048x2048) * X[b] (2048x1024)
    {
        dim3 grid(DD / BN, SS / BM, BB);
        gemm_nn<<<grid, 256>>>(attn, X, ctx,
                               SS, DD, SS, sA, sXD, sXD);
    }
}

// round 4
// speedup vs baseline: 2.0836x; 2.0836x over previous
#include <cuda_runtime.h>
#include <cuda_bf16.h>
#include <math.h>
#include <stdint.h>

// Problem shape (fixed by the dataset)
#define BB 8
#define SS 2048
#define DD 1024

// Scratch (device globals — allocation-guard-safe)
__device__ float g_proj[(size_t)BB * SS * DD];   // proj = X@W^T + b
__device__ float g_xt[(size_t)BB * SS * DD];     // XT[b] = X[b]^T

// ============================================================
// Tensor-core GEMM via mma.sync (sm_80+ PTX — assembles for plain sm_103;
// tcgen05 is unavailable because the harness PTX target lacks the 'a' feature).
// NT GEMM: C[m,n] = sum_k A[m,k]*B[n,k] (+bias[n]), fp32 in/out.
// fp32 emulated as bf16x2 split with 3 tensor products (11,12,21):
// residual ~3*2^-18 per term -> ~4e-4 softmax-weight rel err (< 1e-3).
// CTA tile 128x128, K-chunk 64, double-buffered smem, 8 warps (2m x 4n),
// warp tile 64x32, m16n8k16 fragments via ldmatrix + sw128 swizzle.
// ============================================================

#define TILE_B  16384           // one 128x64 bf16 tile (128B rows, SW128)
#define BUF_B   65536           // A0,A1,B0,B1
#define GEMM_SMEM (2 * BUF_B)   // 128 KB

__device__ __forceinline__ uint32_t smem_u32(const void* p) {
    uint32_t a;
    asm("{ .reg .u64 t; cvta.to.shared.u64 t, %1; cvt.u32.u64 %0, t; }" : "=r"(a) : "l"(p));
    return a;
}
__device__ __forceinline__ uint32_t sw128(uint32_t off) {
    return off ^ ((off >> 3) & 0x70);
}
__device__ __forceinline__ void ldsm_x4(uint32_t& r0, uint32_t& r1, uint32_t& r2, uint32_t& r3,
                                        uint32_t addr) {
    asm volatile("ldmatrix.sync.aligned.m8n8.x4.shared.b16 {%0,%1,%2,%3}, [%4];"
                 : "=r"(r0), "=r"(r1), "=r"(r2), "=r"(r3) : "r"(addr));
}
__device__ __forceinline__ void mma16816(float* d, const uint32_t* a, const uint32_t* b) {
    asm volatile(
        "mma.sync.aligned.m16n8k16.row.col.f32.bf16.bf16.f32 "
        "{%0,%1,%2,%3}, {%4,%5,%6,%7}, {%8,%9}, {%0,%1,%2,%3};"
        : "+f"(d[0]), "+f"(d[1]), "+f"(d[2]), "+f"(d[3])
        : "r"(a[0]), "r"(a[1]), "r"(a[2]), "r"(a[3]), "r"(b[0]), "r"(b[1]));
}

// Split one float4 into two bf16x4 (hi, lo-residual) packed as 2x uint32
__device__ __forceinline__ void split2(const float4& v, uint2& hi, uint2& lo) {
    __nv_bfloat162 h0 = __floats2bfloat162_rn(v.x, v.y);
    __nv_bfloat162 h1 = __floats2bfloat162_rn(v.z, v.w);
    float r0 = v.x - __bfloat162float(__low2bfloat16(h0));
    float r1 = v.y - __bfloat162float(__high2bfloat16(h0));
    float r2 = v.z - __bfloat162float(__low2bfloat16(h1));
    float r3 = v.w - __bfloat162float(__high2bfloat16(h1));
    __nv_bfloat162 l0 = __floats2bfloat162_rn(r0, r1);
    __nv_bfloat162 l1 = __floats2bfloat162_rn(r2, r3);
    hi.x = *reinterpret_cast<uint32_t*>(&h0);
    hi.y = *reinterpret_cast<uint32_t*>(&h1);
    lo.x = *reinterpret_cast<uint32_t*>(&l0);
    lo.y = *reinterpret_cast<uint32_t*>(&l1);
}

__global__ __launch_bounds__(256, 1) void gemm_nt_mma(
    const float* __restrict__ A, const float* __restrict__ B,
    float* __restrict__ C, const float* __restrict__ bias,
    int M, int N, int K,
    long long strA, long long strB, long long strC)
{
    extern __shared__ __align__(1024) char smem[];
    const uint32_t sb = smem_u32(smem);
    const int tid = threadIdx.x, wid = tid >> 5, lane = tid & 31;
    const int row0 = blockIdx.y * 128, col0 = blockIdx.x * 128;
    const float* Ab = A + (long long)blockIdx.z * strA;
    const float* Bb = B + (long long)blockIdx.z * strB;
    float*       Cb = C + (long long)blockIdx.z * strC;

    const int wm = wid >> 2, wn = wid & 3;      // 2 x 4 warp grid
    const int m0w = wm * 64, n0w = wn * 32;

    // --- loader indexing (per 32-col sub-chunk): thread covers 16 floats ---
    const int ldr  = tid >> 1;                   // row 0..127
    const int ldc0 = (tid & 1) * 16;             // col base within 32

    // --- ldmatrix lane addressing (byte offsets within a tile) ---
    // A: row = (lane&15), col8 = lane>>4     (per mf: +16 rows; per kstep: +16 cols)
    const uint32_t a_lrow = (uint32_t)(lane & 15);
    const uint32_t a_lc8  = (uint32_t)(lane >> 4) * 8;
    // B: n = (lane&7) + ((lane>>4)&1)*8, k8 = ((lane>>3)&1)*8  (per nfp: +16 rows)
    const uint32_t b_lrow = (uint32_t)((lane & 7) + ((lane >> 4) & 1) * 8);
    const uint32_t b_lk8  = (uint32_t)((lane >> 3) & 1) * 8;

    float acc[4][4][4];
#pragma unroll
    for (int i = 0; i < 4; i++)
#pragma unroll
        for (int j = 0; j < 4; j++)
#pragma unroll
            for (int q = 0; q < 4; q++) acc[i][j][q] = 0.f;

    const int NCH = K >> 6;

    // ---- helpers as lambdas ----
    auto ldg_sub = [&](int ch, int sub, float4* av, float4* bv) {
        const int k0 = (ch << 6) + sub * 32 + ldc0;
        const float* pa = Ab + (size_t)(row0 + ldr) * K + k0;
        const float* pb = Bb + (size_t)(col0 + ldr) * K + k0;
#pragma unroll
        for (int q = 0; q < 4; q++) av[q] = *(const float4*)(pa + 4 * q);
#pragma unroll
        for (int q = 0; q < 4; q++) bv[q] = *(const float4*)(pb + 4 * q);
    };
    auto sts_sub = [&](uint32_t base, int sub, const float4* av, const float4* bv) {
#pragma unroll
        for (int q = 0; q < 4; q++) {
            uint32_t off = (uint32_t)(ldr * 128 + (sub * 32 + ldc0 + 4 * q) * 2);
            uint32_t sw  = sw128(off);
            uint2 hi, lo;
            split2(av[q], hi, lo);
            *reinterpret_cast<uint2*>(smem + (base) + sw)            = hi;  // A0
            *reinterpret_cast<uint2*>(smem + (base + TILE_B) + sw)   = lo;  // A1
            split2(bv[q], hi, lo);
            *reinterpret_cast<uint2*>(smem + (base + 2*TILE_B) + sw) = hi;  // B0
            *reinterpret_cast<uint2*>(smem + (base + 3*TILE_B) + sw) = lo;  // B1
        }
    };
    auto mma_half = [&](uint32_t base, int ks0) {
#pragma unroll
        for (int ks = ks0; ks < ks0 + 2; ks++) {
            uint32_t aF[2][4][4], bF[2][4][2];
            // load A frags (levels 0,1; 4 m-frags)
#pragma unroll
            for (int lv = 0; lv < 2; lv++) {
                uint32_t tb = base + lv * TILE_B;
#pragma unroll
                for (int mf = 0; mf < 4; mf++) {
                    uint32_t off = (uint32_t)((m0w + mf * 16 + a_lrow) * 128
                                              + (ks * 16 + a_lc8) * 2);
                    ldsm_x4(aF[lv][mf][0], aF[lv][mf][1], aF[lv][mf][2], aF[lv][mf][3],
                            sb + tb + sw128(off));
                }
            }
            // load B frags (levels 0,1; 4 n-frags via 2 x4-ldmatrix)
#pragma unroll
            for (int lv = 0; lv < 2; lv++) {
                uint32_t tb = base + (2 + lv) * TILE_B;
#pragma unroll
                for (int nfp = 0; nfp < 2; nfp++) {
                    uint32_t off = (uint32_t)((n0w + nfp * 16 + b_lrow) * 128
                                              + (ks * 16 + b_lk8) * 2);
                    uint32_t r0, r1, r2, r3;
                    ldsm_x4(r0, r1, r2, r3, sb + tb + sw128(off));
                    bF[lv][nfp * 2][0] = r0;  bF[lv][nfp * 2][1] = r1;
                    bF[lv][nfp * 2 + 1][0] = r2;  bF[lv][nfp * 2 + 1][1] = r3;
                }
            }
            // 3 products: A0*B0, A0*B1, A1*B0
#pragma unroll
            for (int mf = 0; mf < 4; mf++)
#pragma unroll
                for (int nf = 0; nf < 4; nf++) {
                    mma16816(acc[mf][nf], aF[0][mf], bF[0][nf]);
                    mma16816(acc[mf][nf], aF[0][mf], bF[1][nf]);
                    mma16816(acc[mf][nf], aF[1][mf], bF[0][nf]);
                }
        }
    };

    // ---- prologue: fill buffer 0 ----
    {
        float4 av[4], bv[4];
        ldg_sub(0, 0, av, bv);  sts_sub(0, 0, av, bv);
        ldg_sub(0, 1, av, bv);  sts_sub(0, 1, av, bv);
    }
    __syncthreads();

    // ---- main loop ----
    for (int ch = 0; ch < NCH; ch++) {
        const uint32_t cur = (uint32_t)((ch & 1) * BUF_B);
        const uint32_t nxt = (uint32_t)(((ch + 1) & 1) * BUF_B);
        const bool pf = (ch + 1 < NCH);
        float4 av[4], bv[4];

        if (pf) ldg_sub(ch + 1, 0, av, bv);
        mma_half(cur, 0);
        if (pf) sts_sub(nxt, 0, av, bv);

        if (pf) ldg_sub(ch + 1, 1, av, bv);
        mma_half(cur, 2);
        if (pf) sts_sub(nxt, 1, av, bv);

        __syncthreads();
    }

    // ---- epilogue: stage accums -> smem -> coalesced STG (+bias) ----
    float* eps = reinterpret_cast<float*>(smem);   // [128][132]
    const int g = lane >> 2, c = lane & 3;
#pragma unroll
    for (int mf = 0; mf < 4; mf++)
#pragma unroll
        for (int nf = 0; nf < 4; nf++) {
            int r = m0w + mf * 16 + g;
            int cc = n0w + nf * 8 + 2 * c;
            *reinterpret_cast<float2*>(&eps[r * 132 + cc]) =
                make_float2(acc[mf][nf][0], acc[mf][nf][1]);
            *reinterpret_cast<float2*>(&eps[(r + 8) * 132 + cc]) =
                make_float2(acc[mf][nf][2], acc[mf][nf][3]);
        }
    __syncthreads();

#pragma unroll
    for (int it = 0; it < 16; it++) {
        int idx = tid + it * 256;
        int row = idx >> 5;
        int c4  = (idx & 31) << 2;
        float4 v = *reinterpret_cast<float4*>(&eps[row * 132 + c4]);
        if (bias) {
            float4 bz = *reinterpret_cast<const float4*>(&bias[col0 + c4]);
            v.x += bz.x; v.y += bz.y; v.z += bz.z; v.w += bz.w;
        }
        *reinterpret_cast<float4*>(&Cb[(size_t)(row0 + row) * N + col0 + c4]) = v;
    }
}

// ============================================================
// Batched 32x32 transpose: XT[b][d][s] = X[b][s][d]
// ============================================================
__global__ __launch_bounds__(256) void transpose_x(const float* __restrict__ X,
                                                   float* __restrict__ XT)
{
    __shared__ float t[32][33];
    const int b = blockIdx.z;
    const int s0 = blockIdx.x * 32, d0 = blockIdx.y * 32;
    const float* Xb = X + (size_t)b * SS * DD;
    float* Tb = XT + (size_t)b * SS * DD;
    const int tx = threadIdx.x, ty = threadIdx.y;
#pragma unroll
    for (int j = 0; j < 4; j++)
        t[ty + 8 * j][tx] = Xb[(size_t)(s0 + ty + 8 * j) * DD + d0 + tx];
    __syncthreads();
#pragma unroll
    for (int j = 0; j < 4; j++)
        Tb[(size_t)(d0 + ty + 8 * j) * SS + s0 + tx] = t[tx][ty + 8 * j];
}

// ============================================================
// In-place row softmax (rows of length SS = 2048)
// ============================================================
__device__ __forceinline__ float warp_max(float v) {
#pragma unroll
    for (int o = 16; o > 0; o >>= 1) v = fmaxf(v, __shfl_xor_sync(0xFFFFFFFFu, v, o));
    return v;
}
__device__ __forceinline__ float warp_sum(float v) {
#pragma unroll
    for (int o = 16; o > 0; o >>= 1) v += __shfl_xor_sync(0xFFFFFFFFu, v, o);
    return v;
}

__global__ __launch_bounds__(256) void softmax_rows(float* __restrict__ attn)
{
    __shared__ float red[8];
    float* row = attn + (long long)blockIdx.x * SS;
    const int tid = threadIdx.x, lane = tid & 31, wid = tid >> 5;

    float4 v[2];
    v[0] = *reinterpret_cast<const float4*>(&row[tid * 4]);
    v[1] = *reinterpret_cast<const float4*>(&row[(tid + 256) * 4]);

    float mx = -INFINITY;
#pragma unroll
    for (int i = 0; i < 2; i++)
        mx = fmaxf(mx, fmaxf(fmaxf(v[i].x, v[i].y), fmaxf(v[i].z, v[i].w)));
    mx = warp_max(mx);
    if (lane == 0) red[wid] = mx;
    __syncthreads();
    if (wid == 0) {
        float t = (lane < 8) ? red[lane] : -INFINITY;
        t = warp_max(t);
        if (lane == 0) red[0] = t;
    }
    __syncthreads();
    mx = red[0];
    __syncthreads();

    float s = 0.f;
#pragma unroll
    for (int i = 0; i < 2; i++) {
        v[i].x = expf(v[i].x - mx); s += v[i].x;
        v[i].y = expf(v[i].y - mx); s += v[i].y;
        v[i].z = expf(v[i].z - mx); s += v[i].z;
        v[i].w = expf(v[i].w - mx); s += v[i].w;
    }
    s = warp_sum(s);
    if (lane == 0) red[wid] = s;
    __syncthreads();
    if (wid == 0) {
        float t = (lane < 8) ? red[lane] : 0.0f;
        t = warp_sum(t);
        if (lane == 0) red[0] = t;
    }
    __syncthreads();
    float inv = 1.0f / red[0];

#pragma unroll
    for (int i = 0; i < 2; i++) { v[i].x *= inv; v[i].y *= inv; v[i].z *= inv; v[i].w *= inv; }
    *reinterpret_cast<float4*>(&row[tid * 4])         = v[0];
    *reinterpret_cast<float4*>(&row[(tid + 256) * 4]) = v[1];
}

// ============================================================
// kernel_launch
// ============================================================
extern "C" void kernel_launch(void* const* d_in, const int* in_sizes, int n_in,
                              void* d_out, int out_size)
{
    const float* X    = (const float*)d_in[0];
    const float* W    = (const float*)d_in[1];
    const float* bias = (const float*)d_in[2];

    float* ctx  = (float*)d_out;                           // [8,2048,1024]
    float* attn = (float*)d_out + (size_t)BB * SS * DD;    // [8,2048,2048]

    float *proj = nullptr, *xt = nullptr;
    cudaGetSymbolAddress((void**)&proj, g_proj);
    cudaGetSymbolAddress((void**)&xt, g_xt);

    cudaFuncSetAttribute(gemm_nt_mma, cudaFuncAttributeMaxDynamicSharedMemorySize, GEMM_SMEM);

    const long long sXD = (long long)SS * DD;
    const long long sAA = (long long)SS * SS;

    // XT[b] = X[b]^T (GEMM3 in NT form)
    {
        dim3 grid(SS / 32, DD / 32, BB);
        transpose_x<<<grid, dim3(32, 8)>>>(X, xt);
    }
    // GEMM1: proj = X[16384,1024] * W^T + b
    {
        dim3 grid(DD / 128, (BB * SS) / 128, 1);
        gemm_nt_mma<<<grid, 256, GEMM_SMEM>>>(X, W, proj, bias, BB * SS, DD, DD, 0, 0, 0);
    }
    // GEMM2: attn[b] = X[b] * proj[b]^T
    {
        dim3 grid(SS / 128, SS / 128, BB);
        gemm_nt_mma<<<grid, 256, GEMM_SMEM>>>(X, proj, attn, nullptr, SS, SS, DD, sXD, sXD, sAA);
    }
    // Softmax in place
    softmax_rows<<<BB * SS, 256>>>(attn);
    // GEMM3: ctx[b] = attn[b] * XT[b]^T
    {
        dim3 grid(DD / 128, SS / 128, BB);
        gemm_nt_mma<<<grid, 256, GEMM_SMEM>>>(attn, xt, ctx, nullptr, SS, DD, SS, sAA, sXD, sXD);
    }
}